// round 1
// baseline (speedup 1.0000x reference)
#include <cuda_runtime.h>

// MLP: 64 -> 4 -> 8 -> 8 -> 32, sigmoid after each layer. fp32.
// Memory-bound: 256MB in + 128MB out. Strategy:
//  - coalesced float4 tile load into padded shared (row stride 17 float4)
//  - per-thread row compute, weights broadcast from shared via float4
//  - output staged in padded shared (row stride 9 float4), coalesced store

#define TPB 128           // threads (= rows) per block
#define XPAD 17           // float4 per padded x row  (16 data + 1 pad)
#define OPAD 9            // float4 per padded out row (8 data + 1 pad)

// shared weight layout (float offsets)
#define OFF_W0 0      // [4][64]   256
#define OFF_B0 256    // [4]
#define OFF_W1 260    // [8][4]    32
#define OFF_B1 292    // [8]
#define OFF_W2 300    // [8][8]    64
#define OFF_B2 364    // [8]
#define OFF_W3 372    // [32][8]   256
#define OFF_B3 628    // [32]
#define W_TOT  660

__device__ __forceinline__ float sigmoidf_fast(float x) {
    return __fdividef(1.0f, 1.0f + __expf(-x));
}

__device__ __forceinline__ float dot4(float4 a, float4 b) {
    float s = a.x * b.x;
    s = fmaf(a.y, b.y, s);
    s = fmaf(a.z, b.z, s);
    s = fmaf(a.w, b.w, s);
    return s;
}

__global__ void __launch_bounds__(TPB)
mlp_kernel(const float* __restrict__ x,
           const float* __restrict__ W0, const float* __restrict__ b0,
           const float* __restrict__ W1, const float* __restrict__ b1,
           const float* __restrict__ W2, const float* __restrict__ b2,
           const float* __restrict__ W3, const float* __restrict__ b3,
           float* __restrict__ out, int batch)
{
    __shared__ __align__(16) float4 tile[TPB * XPAD];   // 34816 B, reused for output
    __shared__ __align__(16) float sW[W_TOT];           // 2640 B

    const int tid = threadIdx.x;

    // ---- load weights into shared (broadcast source) ----
    for (int i = tid; i < 256; i += TPB) sW[OFF_W0 + i] = W0[i];
    if (tid < 4)  sW[OFF_B0 + tid] = b0[tid];
    if (tid < 32) sW[OFF_W1 + tid] = W1[tid];
    if (tid < 8)  sW[OFF_B1 + tid] = b1[tid];
    if (tid < 64) sW[OFF_W2 + tid] = W2[tid];
    if (tid < 8)  sW[OFF_B2 + tid] = b2[tid];
    for (int i = tid; i < 256; i += TPB) sW[OFF_W3 + i] = W3[i];
    if (tid < 32) sW[OFF_B3 + tid] = b3[tid];

    // ---- coalesced load of x tile: TPB rows x 16 float4 ----
    const float4* __restrict__ x4 = (const float4*)x;
    const int base4  = blockIdx.x * (TPB * 16);
    const int lim4   = batch * 16;
    #pragma unroll
    for (int it = 0; it < 16; ++it) {
        int idx = base4 + it * TPB + tid;
        if (idx < lim4) {
            int local = idx - base4;
            int r = local >> 4;
            int c = local & 15;
            tile[r * XPAD + c] = x4[idx];
        }
    }
    __syncthreads();

    const int row = blockIdx.x * TPB + tid;
    const bool active = (row < batch);

    float h1[8];
    float h2[8];

    if (active) {
        // ---- layer 0: 64 -> 4 ----
        float acc0[4];
        #pragma unroll
        for (int j = 0; j < 4; ++j) acc0[j] = sW[OFF_B0 + j];
        const float4* myrow = &tile[tid * XPAD];
        #pragma unroll
        for (int c = 0; c < 16; ++c) {
            float4 xv = myrow[c];
            #pragma unroll
            for (int j = 0; j < 4; ++j) {
                float4 w = *(const float4*)&sW[OFF_W0 + j * 64 + c * 4];
                acc0[j] = fmaf(xv.x, w.x, acc0[j]);
                acc0[j] = fmaf(xv.y, w.y, acc0[j]);
                acc0[j] = fmaf(xv.z, w.z, acc0[j]);
                acc0[j] = fmaf(xv.w, w.w, acc0[j]);
            }
        }
        float4 h0;
        h0.x = sigmoidf_fast(acc0[0]);
        h0.y = sigmoidf_fast(acc0[1]);
        h0.z = sigmoidf_fast(acc0[2]);
        h0.w = sigmoidf_fast(acc0[3]);

        // ---- layer 1: 4 -> 8 ----
        #pragma unroll
        for (int j = 0; j < 8; ++j) {
            float4 w = *(const float4*)&sW[OFF_W1 + j * 4];
            h1[j] = sigmoidf_fast(sW[OFF_B1 + j] + dot4(h0, w));
        }

        // ---- layer 2: 8 -> 8 ----
        #pragma unroll
        for (int j = 0; j < 8; ++j) {
            float4 wa = *(const float4*)&sW[OFF_W2 + j * 8];
            float4 wb = *(const float4*)&sW[OFF_W2 + j * 8 + 4];
            float4 ha = make_float4(h1[0], h1[1], h1[2], h1[3]);
            float4 hb = make_float4(h1[4], h1[5], h1[6], h1[7]);
            h2[j] = sigmoidf_fast(sW[OFF_B2 + j] + dot4(ha, wa) + dot4(hb, wb));
        }
    }

    // all x reads complete before reusing `tile` for output
    __syncthreads();

    if (active) {
        // ---- layer 3: 8 -> 32, write to padded shared out tile ----
        float4 ha = make_float4(h2[0], h2[1], h2[2], h2[3]);
        float4 hb = make_float4(h2[4], h2[5], h2[6], h2[7]);
        #pragma unroll
        for (int g = 0; g < 8; ++g) {
            float o[4];
            #pragma unroll
            for (int k = 0; k < 4; ++k) {
                int j = g * 4 + k;
                float4 wa = *(const float4*)&sW[OFF_W3 + j * 8];
                float4 wb = *(const float4*)&sW[OFF_W3 + j * 8 + 4];
                o[k] = sigmoidf_fast(sW[OFF_B3 + j] + dot4(ha, wa) + dot4(hb, wb));
            }
            tile[tid * OPAD + g] = make_float4(o[0], o[1], o[2], o[3]);
        }
    }
    __syncthreads();

    // ---- coalesced store: TPB rows x 8 float4 ----
    float4* __restrict__ out4 = (float4*)out;
    const int obase4 = blockIdx.x * (TPB * 8);
    const int olim4  = batch * 8;
    #pragma unroll
    for (int it = 0; it < 8; ++it) {
        int idx = obase4 + it * TPB + tid;
        if (idx < olim4) {
            int local = idx - obase4;
            int r = local >> 3;
            int c = local & 7;
            out4[idx] = tile[r * OPAD + c];
        }
    }
}

extern "C" void kernel_launch(void* const* d_in, const int* in_sizes, int n_in,
                              void* d_out, int out_size)
{
    const float* x  = (const float*)d_in[0];
    const float* W0 = (const float*)d_in[1];
    const float* b0 = (const float*)d_in[2];
    const float* W1 = (const float*)d_in[3];
    const float* b1 = (const float*)d_in[4];
    const float* W2 = (const float*)d_in[5];
    const float* b2 = (const float*)d_in[6];
    const float* W3 = (const float*)d_in[7];
    const float* b3 = (const float*)d_in[8];
    float* out = (float*)d_out;

    int batch = in_sizes[0] / 64;
    int grid = (batch + TPB - 1) / TPB;
    mlp_kernel<<<grid, TPB>>>(x, W0, b0, W1, b1, W2, b2, W3, b3, out, batch);
}